// round 1
// baseline (speedup 1.0000x reference)
#include <cuda_runtime.h>
#include <cuda_bf16.h>
#include <cstdint>

#define BZ 32
#define CH 64
#define HH 128
#define WW 128
#define TILE_H 8
#define TILE_W 32
#define MP_STRIDE 264   // words per c2-plane (256 pixels + 8 pad) -> conflict-free both ways
#define WP_STRIDE 33    // words per o-row of packed weights

__global__ __launch_bounds__(256, 4)
void denoise_fused_kernel(const float* __restrict__ x,
                          const float* __restrict__ conv_w,
                          const float* __restrict__ conv_b,
                          float* __restrict__ out) {
    __shared__ uint32_t Mp[32 * MP_STRIDE];   // box-mean bf16x2, [c/2][pixel]
    __shared__ uint32_t Wp[64 * WP_STRIDE];   // weights  bf16x2, [o][c/2]
    __shared__ float    BiasS[64];

    const int tid  = threadIdx.x;
    const int warp = tid >> 5;
    const int lane = tid & 31;

    const int b  = blockIdx.z;
    const int h0 = blockIdx.y * TILE_H;
    const int w0 = blockIdx.x * TILE_W;

    // ---------- phase 0: stage weights (bf16x2) + bias into smem ----------
    for (int i = tid; i < 64 * 32; i += 256) {
        const int o = i >> 5, c2 = i & 31;
        const float2 wv = reinterpret_cast<const float2*>(conv_w)[o * 32 + c2];
        __nv_bfloat162 pk = __halves2bfloat162(__float2bfloat16_rn(wv.x),
                                               __float2bfloat16_rn(wv.y));
        Wp[o * WP_STRIDE + c2] = *reinterpret_cast<uint32_t*>(&pk);
    }
    if (tid < 64) BiasS[tid] = conv_b[tid];

    // ---------- phase 1: edge-clipped 3x3 box mean -> bf16x2 smem ----------
    // warp handles channel pair (ca, ca+1); lanes = 32 columns of the tile.
    const float* xb = x + (size_t)b * CH * HH * WW;
    const int   w    = w0 + lane;
    const float invw = (w == 0 || w == WW - 1) ? 0.5f : (1.0f / 3.0f);

    for (int chunk = 0; chunk < 4; chunk++) {
        const int ca = chunk * 16 + warp * 2;
        const float* pa  = xb + ca * (HH * WW);
        const float* pb2 = pa + (HH * WW);
        float hsA[10], hsB[10];
        #pragma unroll
        for (int i = 0; i < 10; i++) {
            const int r = h0 - 1 + i;
            const bool rin = (r >= 0) && (r < HH);
            float va = 0.f, vb = 0.f;
            if (rin) { va = pa[r * WW + w]; vb = pb2[r * WW + w]; }
            float la = __shfl_up_sync(0xffffffffu, va, 1);
            float lb = __shfl_up_sync(0xffffffffu, vb, 1);
            float ra = __shfl_down_sync(0xffffffffu, va, 1);
            float rb = __shfl_down_sync(0xffffffffu, vb, 1);
            if (lane == 0) {
                la = (rin && w0 > 0) ? pa[r * WW + w0 - 1]  : 0.f;
                lb = (rin && w0 > 0) ? pb2[r * WW + w0 - 1] : 0.f;
            }
            if (lane == 31) {
                ra = (rin && (w0 + TILE_W) < WW) ? pa[r * WW + w0 + TILE_W]  : 0.f;
                rb = (rin && (w0 + TILE_W) < WW) ? pb2[r * WW + w0 + TILE_W] : 0.f;
            }
            hsA[i] = la + va + ra;
            hsB[i] = lb + vb + rb;
        }
        #pragma unroll
        for (int ro = 0; ro < TILE_H; ro++) {
            const int h = h0 + ro;
            const float invh = (h == 0 || h == HH - 1) ? 0.5f : (1.0f / 3.0f);
            const float s = invh * invw;
            const float ma = (hsA[ro] + hsA[ro + 1] + hsA[ro + 2]) * s;
            const float mb = (hsB[ro] + hsB[ro + 1] + hsB[ro + 2]) * s;
            __nv_bfloat162 pk = __halves2bfloat162(__float2bfloat16_rn(ma),
                                                   __float2bfloat16_rn(mb));
            Mp[(ca >> 1) * MP_STRIDE + ro * 32 + lane] =
                *reinterpret_cast<uint32_t*>(&pk);
        }
    }
    __syncthreads();

    // ---------- phase 2: channel GEMM on tensor pipe ----------
    // D[o, p] = sum_c W[o,c] * mean[p,c];   M=64 (o), N=256 (pixels), K=64 (c)
    // warp -> m-tile (warp>>1), pixel half (warp&1)*128.
    const int o0    = (warp >> 1) * 16;
    const int pbase = (warp & 1) * 128;
    const int lq = lane >> 2;   // 0..7
    const int lr = lane & 3;    // 0..3

    uint32_t a[4][4];
    #pragma unroll
    for (int kk = 0; kk < 4; kk++) {
        a[kk][0] = Wp[(o0 + lq)     * WP_STRIDE + kk * 8 + lr];
        a[kk][1] = Wp[(o0 + 8 + lq) * WP_STRIDE + kk * 8 + lr];
        a[kk][2] = Wp[(o0 + lq)     * WP_STRIDE + kk * 8 + 4 + lr];
        a[kk][3] = Wp[(o0 + 8 + lq) * WP_STRIDE + kk * 8 + 4 + lr];
    }
    const int oA = o0 + lq, oB = oA + 8;
    const float biasA = BiasS[oA];
    const float biasB = BiasS[oB];
    const size_t chanA = ((size_t)b * CH + oA) * (size_t)(HH * WW);

    #pragma unroll
    for (int nt = 0; nt < 16; nt++) {
        const int n0 = pbase + nt * 8;
        float acc0 = 0.f, acc1 = 0.f, acc2 = 0.f, acc3 = 0.f;
        #pragma unroll
        for (int kk = 0; kk < 4; kk++) {
            const uint32_t b0 = Mp[(kk * 8 + lr)     * MP_STRIDE + n0 + lq];
            const uint32_t b1 = Mp[(kk * 8 + 4 + lr) * MP_STRIDE + n0 + lq];
            asm volatile(
                "mma.sync.aligned.m16n8k16.row.col.f32.bf16.bf16.f32 "
                "{%0,%1,%2,%3}, {%4,%5,%6,%7}, {%8,%9}, {%0,%1,%2,%3};\n"
                : "+f"(acc0), "+f"(acc1), "+f"(acc2), "+f"(acc3)
                : "r"(a[kk][0]), "r"(a[kk][1]), "r"(a[kk][2]), "r"(a[kk][3]),
                  "r"(b0), "r"(b1));
        }
        // epilogue: out = x + bias + D   (fragment: rows oA/oB, cols p0,p0+1)
        const int p0 = n0 + lr * 2;
        const int hh = h0 + (p0 >> 5);
        const int wc = w0 + (p0 & 31);
        const size_t off = chanA + (size_t)(hh * WW + wc);
        const float2 xa = *reinterpret_cast<const float2*>(x + off);
        const float2 xc = *reinterpret_cast<const float2*>(x + off + 8 * HH * WW);
        float2 oa, ob;
        oa.x = xa.x + biasA + acc0;
        oa.y = xa.y + biasA + acc1;
        ob.x = xc.x + biasB + acc2;
        ob.y = xc.y + biasB + acc3;
        *reinterpret_cast<float2*>(out + off)               = oa;
        *reinterpret_cast<float2*>(out + off + 8 * HH * WW) = ob;
    }
}

extern "C" void kernel_launch(void* const* d_in, const int* in_sizes, int n_in,
                              void* d_out, int out_size) {
    const float* x      = (const float*)d_in[0];
    const float* conv_w = (const float*)d_in[1];
    const float* conv_b = (const float*)d_in[2];
    float* out = (float*)d_out;
    dim3 grid(WW / TILE_W, HH / TILE_H, BZ);   // 4 x 16 x 32 = 2048 CTAs
    denoise_fused_kernel<<<grid, 256>>>(x, conv_w, conv_b, out);
}